// round 5
// baseline (speedup 1.0000x reference)
#include <cuda_runtime.h>

// ---------------------------------------------------------------------------
// CGCNN: B=16, N=1024, M=12, F=64, BF=128, N_CONV=3, VOCAB=100
// total@W = x@W1 + gather(x@W2) + bond@W3 ; proj fused into conv/embed.
// Y/S scratch is DOUBLE-BUFFERED: layer l reads buf (l&1), fused proj for
// layer l+1 writes buf ((l+1)&1) -> no cross-block read/write race.
// ---------------------------------------------------------------------------

#define BN_ALPHA 0.99950037f   // 1/sqrt(1+1e-3)

__device__ float g_X0[16 * 1024 * 64];
__device__ float g_X1[16 * 1024 * 64];
__device__ float g_Y1[2][16 * 1024 * 64];
__device__ float g_Y2[2][16 * 1024 * 64];
__device__ float g_S1[2][16 * 1024];
__device__ float g_S2[2][16 * 1024];

// ---- f32x2 packed FMA helpers ---------------------------------------------
__device__ __forceinline__ void fma2(unsigned long long& d,
                                     unsigned long long a,
                                     unsigned long long b) {
    asm("fma.rn.f32x2 %0, %1, %2, %0;" : "+l"(d) : "l"(a), "l"(b));
}
__device__ __forceinline__ float2 up2(unsigned long long v) {
    unsigned lo, hi;
    asm("mov.b64 {%0, %1}, %2;" : "=r"(lo), "=r"(hi) : "l"(v));
    float2 r;
    r.x = __uint_as_float(lo);
    r.y = __uint_as_float(hi);
    return r;
}
__device__ __forceinline__ void cp16(unsigned smem, const void* g) {
    asm volatile("cp.async.cg.shared.global [%0], [%1], 16;" ::"r"(smem), "l"(g));
}

// ---------------------------------------------------------------------------
// Projection helper: 8 rows of x (smem, stride 68) -> Y1/Y2/S1/S2 buffer yb
// c2 in [0,130): 0-63 -> Y1 col, 64-127 -> Y2 col, 128 -> S1, 129 -> S2
// ---------------------------------------------------------------------------
__device__ __forceinline__ void proj8(const float* __restrict__ xs, int bn0,
                                      int r0, int c2, int yb,
                                      const float* __restrict__ cwn,
                                      const float* __restrict__ fwn) {
    const float* wp;
    int st;
    if (c2 < 64) {
        wp = cwn + c2;
        st = 64;
    } else if (c2 < 128) {
        wp = cwn + 64 * 64 + (c2 - 64);
        st = 64;
    } else {
        wp = fwn + (c2 - 128) * 64;
        st = 1;
    }
    float acc[8] = {0.f, 0.f, 0.f, 0.f, 0.f, 0.f, 0.f, 0.f};
#pragma unroll 8
    for (int k = 0; k < 64; k++) {
        float wv = __ldg(wp + k * st);
#pragma unroll
        for (int rr = 0; rr < 8; rr++) acc[rr] += xs[(r0 + rr) * 68 + k] * wv;
    }
    if (c2 < 64) {
#pragma unroll
        for (int rr = 0; rr < 8; rr++)
            g_Y1[yb][(bn0 + r0 + rr) * 64 + c2] = acc[rr];
    } else if (c2 < 128) {
#pragma unroll
        for (int rr = 0; rr < 8; rr++)
            g_Y2[yb][(bn0 + r0 + rr) * 64 + (c2 - 64)] = acc[rr];
    } else if (c2 == 128) {
#pragma unroll
        for (int rr = 0; rr < 8; rr++) g_S1[yb][bn0 + r0 + rr] = acc[rr];
    } else {
#pragma unroll
        for (int rr = 0; rr < 8; rr++) g_S2[yb][bn0 + r0 + rr] = acc[rr];
    }
}

// ---------------------------------------------------------------------------
// Embedding gather + layer-0 projection (writes Y/S buffer 0).
// ---------------------------------------------------------------------------
__global__ void __launch_bounds__(256) embed_proj_k(
    const int* __restrict__ types, const float* __restrict__ emb,
    const float* __restrict__ cwn, const float* __restrict__ fwn) {
    __shared__ float xs[16 * 68];
    int tid = threadIdx.x;
    int bn0 = blockIdx.x * 16;
    {
        int r = tid >> 4, q = tid & 15;
        int node = bn0 + r;
        int t = types[node];
        float4 v = *(const float4*)(emb + t * 64 + q * 4);
        *(float4*)(xs + r * 68 + q * 4) = v;
        *(float4*)(g_X0 + node * 64 + q * 4) = v;
    }
    __syncthreads();
    if (tid < 130) {
        proj8(xs, bn0, 0, tid, 0, cwn, fwn);
        proj8(xs, bn0, 8, tid, 0, cwn, fwn);
    }
}

// ---------------------------------------------------------------------------
// Main conv: one block = 16 atoms (192 rows), 512 threads.
//  GEMM C[192][64] = bond[192][128] @ cw3 via k-split f32x2:
//    warp w: row-group rg=w&1 (96 rows), col-group cg=w>>1 (8 cols)
//    per thread: 3 rows x 8 cols, acc = f32x2 (even-k, odd-k partials)
//  Epilogue: +y1+y2[nbr]+cb, BN, relu, softmax(filt), weighted mean, BN,
//            residual relu -> Xn; then fused next-layer proj (buffer ywr).
// ---------------------------------------------------------------------------
#define CONV_SMEM ((25344 + 8448 + 128 + 192 + 1088 + 192) * 4)

__global__ void __launch_bounds__(512, 1) conv_k(
    int flip, int yrd, int ywr, const float* __restrict__ bond,
    const int* __restrict__ nbrl, const float* __restrict__ cw3,
    const float* __restrict__ fw3, const float* __restrict__ cb,
    const float* __restrict__ fb, const float* __restrict__ bag,
    const float* __restrict__ bab, const float* __restrict__ bbg,
    const float* __restrict__ bbb, int do_proj,
    const float* __restrict__ cwn, const float* __restrict__ fwn) {
    extern __shared__ float sm[];
    float* bs = sm;                    // 192 x 132 bond tile (k contiguous)
    float* ws2 = sm + 25344;           // 64 x 132 weights, C-MAJOR: ws2[c][k]
    float* fs = ws2 + 8448;            // 128 filter weights
    float* ft = fs + 128;              // 192 logits / softmax weights
    float* xb = ft + 192;              // 16 x 68 new-x stash for fused proj
    int* nb = (int*)(xb + 1088);       // 192 neighbor ids

    const float* Xc = flip ? g_X1 : g_X0;
    float* Xn = flip ? g_X0 : g_X1;
    const float* Y1r = g_Y1[yrd];
    const float* Y2r = g_Y2[yrd];
    const float* S1r = g_S1[yrd];
    const float* S2r = g_S2[yrd];

    int tid = threadIdx.x;
    int b = blockIdx.x >> 6;
    int n0 = (blockIdx.x & 63) << 4;
    int bn0 = b * 1024 + n0;
    const float* gb = bond + (size_t)bn0 * 12 * 128;

    unsigned bs_s = (unsigned)__cvta_generic_to_shared(bs);
    // two committed halves of the 96KB bond tile
    for (int h = 0; h < 2; h++) {
        for (int t = tid; t < 3072; t += 512) {
            int r = t >> 4, q = t & 15;
            int k = h * 64 + q * 4;
            cp16(bs_s + (r * 132 + k) * 4, gb + r * 128 + k);
        }
        asm volatile("cp.async.commit_group;");
    }
    // transpose-load core weights into c-major tile (coalesced LDG)
    for (int t = tid; t < 8192; t += 512) {
        int k = t >> 6, c = t & 63;
        ws2[c * 132 + k] = cw3[t];     // cw3[k*64+c] == cw3[t]
    }
    if (tid < 128) fs[tid] = fw3[tid];

    int lane = tid & 31, w = tid >> 5;
    int rg = w & 1, cg = w >> 1;
    int rbase = rg * 96 + lane;
    const float* wsb = ws2 + cg * 8 * 132;

    unsigned long long acc[3][8];
#pragma unroll
    for (int i = 0; i < 3; i++)
#pragma unroll
        for (int j = 0; j < 8; j++) acc[i][j] = 0ull;

    for (int half = 0; half < 2; half++) {
        if (half == 0)
            asm volatile("cp.async.wait_group 1;");
        else
            asm volatile("cp.async.wait_group 0;");
        __syncthreads();
#pragma unroll 2
        for (int kk = 0; kk < 64; kk += 4) {
            int k0 = half * 64 + kk;
            ulonglong2 a[3];
#pragma unroll
            for (int i = 0; i < 3; i++)
                a[i] = *(const ulonglong2*)(bs + (rbase + 32 * i) * 132 + k0);
#pragma unroll
            for (int j = 0; j < 8; j++) {
                ulonglong2 bv = *(const ulonglong2*)(wsb + j * 132 + k0);
#pragma unroll
                for (int i = 0; i < 3; i++) {
                    fma2(acc[i][j], a[i].x, bv.x);
                    fma2(acc[i][j], a[i].y, bv.y);
                }
            }
        }
    }

    // filter logits (reads bond tile before it is overwritten by Cs)
    if (tid < 192) {
        int row = tid;
        int a_ = row / 12, m = row - a_ * 12;
        int nglob = bn0 + a_;
        int nbr = nbrl[nglob * 12 + m];
        nb[row] = nbr;
        float acc2 = 0.f;
#pragma unroll 8
        for (int k = 0; k < 128; k += 4) {
            float4 bvv = *(const float4*)(bs + row * 132 + k);
            float4 fv = *(const float4*)(fs + k);
            acc2 += bvv.x * fv.x + bvv.y * fv.y + bvv.z * fv.z + bvv.w * fv.w;
        }
        ft[row] = acc2 + S1r[nglob] + S2r[b * 1024 + nbr] + fb[0];
    }
    __syncthreads();

    // softmax over m (folding the 1/12 mean)
    if (tid < 16) {
        int base = tid * 12;
        float mx = -1e30f;
#pragma unroll
        for (int m = 0; m < 12; m++) mx = fmaxf(mx, ft[base + m]);
        float s = 0.f;
#pragma unroll
        for (int m = 0; m < 12; m++) s += expf(ft[base + m] - mx);
        float inv = 1.f / (12.f * s);
#pragma unroll
        for (int m = 0; m < 12; m++)
            ft[base + m] = expf(ft[base + m] - mx) * inv;
    }

    // core epilogue: C + y1 + y2[nbr] + cb -> BN -> relu -> Cs (reuses bs)
    float* Cs = bs;   // 192 x 65
#pragma unroll
    for (int i = 0; i < 3; i++) {
        int row = rbase + 32 * i;
        int a_ = row / 12;
        int nglob = bn0 + a_;
        int nbr = nb[row];
        const float* y1p = Y1r + nglob * 64;
        const float* y2p = Y2r + (b * 1024 + nbr) * 64;
#pragma unroll
        for (int j = 0; j < 8; j++) {
            int c = cg * 8 + j;
            float2 t = up2(acc[i][j]);
            float v = t.x + t.y;   // reduce k-split partials
            v += y1p[c] + y2p[c] + __ldg(cb + c);
            v = fmaxf(__ldg(bag + c) * (v * BN_ALPHA) + __ldg(bab + c), 0.f);
            Cs[row * 65 + c] = v;
        }
    }
    __syncthreads();

    // weighted mean over m, BN, residual relu; stash xn for fused proj
#pragma unroll
    for (int q = 0; q < 2; q++) {
        int idx = tid + 512 * q;   // < 1024
        int a_ = idx >> 6, c = idx & 63;
        float s = 0.f;
#pragma unroll
        for (int m = 0; m < 12; m++)
            s += ft[a_ * 12 + m] * Cs[(a_ * 12 + m) * 65 + c];
        s = __ldg(bbg + c) * (s * BN_ALPHA) + __ldg(bbb + c);
        int gi = (bn0 + a_) * 64 + c;
        float xv = fmaxf(Xc[gi] + s, 0.f);
        Xn[gi] = xv;
        xb[a_ * 68 + c] = xv;
    }

    // fused next-layer projection into the WRITE buffer (no race: readers of
    // this launch use yrd, writers use ywr != yrd)
    if (do_proj) {
        __syncthreads();
        if (tid < 260) {
            int rg2 = (tid >= 130) ? 1 : 0;
            int c2 = tid - rg2 * 130;
            proj8(xb, bn0, rg2 * 8, c2, ywr, cwn, fwn);
        }
    }
}

// ---------------------------------------------------------------------------
// Final: crys = relu(gather(x, target_index)); out = relu(crys@dense_w + db)
// ---------------------------------------------------------------------------
__global__ void __launch_bounds__(256) final_k(const int* __restrict__ tix,
                                               const float* __restrict__ dw,
                                               const float* __restrict__ db,
                                               float* __restrict__ out) {
    __shared__ float cs[64 * 68];
    __shared__ float wd[64 * 65];
    int b = blockIdx.x, tid = threadIdx.x;
    for (int t = tid; t < 4096; t += 256) {
        int k = t >> 6, f = t & 63;
        wd[k * 65 + f] = dw[t];
    }
    for (int t = tid; t < 1024; t += 256) {
        int j = t >> 4, q = t & 15;
        int ti = tix[b * 64 + j];
        float4 v = *(const float4*)(g_X1 + (b * 1024 + ti) * 64 + q * 4);
        v.x = fmaxf(v.x, 0.f);
        v.y = fmaxf(v.y, 0.f);
        v.z = fmaxf(v.z, 0.f);
        v.w = fmaxf(v.w, 0.f);
        *(float4*)(cs + j * 68 + q * 4) = v;
    }
    __syncthreads();
    for (int t = tid; t < 4096; t += 256) {
        int j = t >> 6, f = t & 63;
        float acc = db[f];
#pragma unroll 8
        for (int k = 0; k < 64; k++) acc += cs[j * 68 + k] * wd[k * 65 + f];
        out[b * 4096 + t] = fmaxf(acc, 0.f);
    }
}

// ---------------------------------------------------------------------------
extern "C" void kernel_launch(void* const* d_in, const int* in_sizes, int n_in,
                              void* d_out, int out_size) {
    const int* atom_types = (const int*)d_in[0];
    const float* bond = (const float*)d_in[1];
    const int* nbrl = (const int*)d_in[2];
    const int* tix = (const int*)d_in[3];
    const float* emb = (const float*)d_in[4];
    const float* core_w = (const float*)d_in[5];
    const float* core_b = (const float*)d_in[6];
    const float* filt_w = (const float*)d_in[7];
    const float* filt_b = (const float*)d_in[8];
    const float* bna_g = (const float*)d_in[9];
    const float* bna_b = (const float*)d_in[10];
    const float* bnb_g = (const float*)d_in[11];
    const float* bnb_b = (const float*)d_in[12];
    const float* dw = (const float*)d_in[13];
    const float* db = (const float*)d_in[14];
    float* out = (float*)d_out;

    cudaFuncSetAttribute(conv_k, cudaFuncAttributeMaxDynamicSharedMemorySize,
                         CONV_SMEM);

    embed_proj_k<<<1024, 256>>>(atom_types, emb, core_w, filt_w);
    for (int l = 0; l < 3; l++) {
        int flip = l & 1;
        int yrd = l & 1;
        int ywr = (l + 1) & 1;
        int do_proj = (l < 2) ? 1 : 0;
        const float* cwn = core_w + (l + 1 < 3 ? (l + 1) : l) * 256 * 64;
        const float* fwn = filt_w + (l + 1 < 3 ? (l + 1) : l) * 256;
        conv_k<<<1024, 512, CONV_SMEM>>>(
            flip, yrd, ywr, bond, nbrl, core_w + l * 256 * 64 + 128 * 64,
            filt_w + l * 256 + 128, core_b + l * 64, filt_b + l,
            bna_g + l * 64, bna_b + l * 64, bnb_g + l * 64, bnb_b + l * 64,
            do_proj, cwn, fwn);
    }
    final_k<<<16, 256>>>(tix, dw, db, out);
}

// round 6
// speedup vs baseline: 1.3174x; 1.3174x over previous
#include <cuda_runtime.h>

// ---------------------------------------------------------------------------
// CGCNN: B=16, N=1024, M=12, F=64, BF=128, N_CONV=3, VOCAB=100
// total@W = x@W1 + gather(x@W2) + bond@W3 ; proj fused into conv/embed.
// Y/S double-buffered across layers (no cross-block race).
// Bond + weights loaded via cp.async.bulk (UBLKCP) under mbarriers.
// ---------------------------------------------------------------------------

#define BN_ALPHA 0.99950037f   // 1/sqrt(1+1e-3)

__device__ float g_X0[16 * 1024 * 64];
__device__ float g_X1[16 * 1024 * 64];
__device__ float g_Y1[2][16 * 1024 * 64];
__device__ float g_Y2[2][16 * 1024 * 64];
__device__ float g_S1[2][16 * 1024];
__device__ float g_S2[2][16 * 1024];
__device__ float g_WT[3][64 * 132];   // transposed+padded core W3 (c-major)
__device__ float g_FW[3][128];        // filter W3

// ---- f32x2 packed FMA helpers ---------------------------------------------
__device__ __forceinline__ void fma2(unsigned long long& d,
                                     unsigned long long a,
                                     unsigned long long b) {
    asm("fma.rn.f32x2 %0, %1, %2, %0;" : "+l"(d) : "l"(a), "l"(b));
}
__device__ __forceinline__ float2 up2(unsigned long long v) {
    unsigned lo, hi;
    asm("mov.b64 {%0, %1}, %2;" : "=r"(lo), "=r"(hi) : "l"(v));
    float2 r;
    r.x = __uint_as_float(lo);
    r.y = __uint_as_float(hi);
    return r;
}

// ---- mbarrier + bulk-copy helpers ------------------------------------------
__device__ __forceinline__ void mbar_init(unsigned mbar, unsigned cnt) {
    asm volatile("mbarrier.init.shared.b64 [%0], %1;" ::"r"(mbar), "r"(cnt)
                 : "memory");
}
__device__ __forceinline__ void mbar_expect(unsigned mbar, unsigned bytes) {
    asm volatile("mbarrier.arrive.expect_tx.shared.b64 _, [%0], %1;" ::"r"(mbar),
                 "r"(bytes)
                 : "memory");
}
__device__ __forceinline__ void mbar_wait(unsigned mbar) {
    asm volatile(
        "{\n\t.reg .pred P;\n\t"
        "W%=:\n\t"
        "mbarrier.try_wait.parity.acquire.cta.shared::cta.b64 P, [%0], 0;\n\t"
        "@!P bra W%=;\n\t}"
        ::"r"(mbar)
        : "memory");
}
__device__ __forceinline__ void bulk_cp(unsigned dst, const void* src,
                                        unsigned bytes, unsigned mbar) {
    asm volatile(
        "cp.async.bulk.shared::cta.global.mbarrier::complete_tx::bytes "
        "[%0], [%1], %2, [%3];" ::"r"(dst),
        "l"(src), "r"(bytes), "r"(mbar)
        : "memory");
}

// ---------------------------------------------------------------------------
// Weight prep: transpose core W3 per layer into c-major padded layout.
// grid 3 blocks x 256 threads.
// ---------------------------------------------------------------------------
__global__ void __launch_bounds__(256) prep_k(const float* __restrict__ cw,
                                              const float* __restrict__ fw) {
    int l = blockIdx.x;
    const float* cw3 = cw + l * 256 * 64 + 128 * 64;
    for (int t = threadIdx.x; t < 8192; t += 256) {
        int k = t >> 6, c = t & 63;
        g_WT[l][c * 132 + k] = cw3[t];
    }
    const float* fw3 = fw + l * 256 + 128;
    if (threadIdx.x < 128) g_FW[l][threadIdx.x] = fw3[threadIdx.x];
}

// ---------------------------------------------------------------------------
// Projection helper: 8 rows of x (smem, stride 68) -> Y1/Y2/S1/S2 buffer yb
// ---------------------------------------------------------------------------
__device__ __forceinline__ void proj8(const float* __restrict__ xs, int bn0,
                                      int r0, int c2, int yb,
                                      const float* __restrict__ cwn,
                                      const float* __restrict__ fwn) {
    const float* wp;
    int st;
    if (c2 < 64) {
        wp = cwn + c2;
        st = 64;
    } else if (c2 < 128) {
        wp = cwn + 64 * 64 + (c2 - 64);
        st = 64;
    } else {
        wp = fwn + (c2 - 128) * 64;
        st = 1;
    }
    float acc[8] = {0.f, 0.f, 0.f, 0.f, 0.f, 0.f, 0.f, 0.f};
#pragma unroll 8
    for (int k = 0; k < 64; k++) {
        float wv = __ldg(wp + k * st);
#pragma unroll
        for (int rr = 0; rr < 8; rr++) acc[rr] += xs[(r0 + rr) * 68 + k] * wv;
    }
    if (c2 < 64) {
#pragma unroll
        for (int rr = 0; rr < 8; rr++)
            g_Y1[yb][(bn0 + r0 + rr) * 64 + c2] = acc[rr];
    } else if (c2 < 128) {
#pragma unroll
        for (int rr = 0; rr < 8; rr++)
            g_Y2[yb][(bn0 + r0 + rr) * 64 + (c2 - 64)] = acc[rr];
    } else if (c2 == 128) {
#pragma unroll
        for (int rr = 0; rr < 8; rr++) g_S1[yb][bn0 + r0 + rr] = acc[rr];
    } else {
#pragma unroll
        for (int rr = 0; rr < 8; rr++) g_S2[yb][bn0 + r0 + rr] = acc[rr];
    }
}

// ---------------------------------------------------------------------------
// Embedding gather + layer-0 projection (writes Y/S buffer 0).
// ---------------------------------------------------------------------------
__global__ void __launch_bounds__(256) embed_proj_k(
    const int* __restrict__ types, const float* __restrict__ emb,
    const float* __restrict__ cwn, const float* __restrict__ fwn) {
    __shared__ float xs[16 * 68];
    int tid = threadIdx.x;
    int bn0 = blockIdx.x * 16;
    {
        int r = tid >> 4, q = tid & 15;
        int node = bn0 + r;
        int t = types[node];
        float4 v = *(const float4*)(emb + t * 64 + q * 4);
        *(float4*)(xs + r * 68 + q * 4) = v;
        *(float4*)(g_X0 + node * 64 + q * 4) = v;
    }
    __syncthreads();
    if (tid < 130) {
        proj8(xs, bn0, 0, tid, 0, cwn, fwn);
        proj8(xs, bn0, 8, tid, 0, cwn, fwn);
    }
}

// ---------------------------------------------------------------------------
// Main conv: one block = 16 atoms (192 rows), 512 threads.
//  Loads: bond tile via 384 x 256B cp.async.bulk (2 k-half mbarrier stages,
//         half 1 overlaps half-0 GEMM); weights via 1 bulk copy.
//  GEMM C[192][64] = bond @ W3, k-split f32x2:
//   16 warps = 4 row-groups (48 rows) x 4 col-groups (16 cols)
//   lane: rt = lane&15 -> 3 consecutive rows, ch = lane>>4 -> 8-col half
//  Epilogue: +y1+y2[nbr]+cb, BN, relu, softmax(filt), weighted mean, BN,
//            residual relu -> Xn; fused next-layer proj (buffer ywr).
// ---------------------------------------------------------------------------
// smem floats: bs 25344 | ws2 8448 | fs 128 | ft 192 | xb 1088 | nb 192 |
//              pb 320 | mbar 4
#define CONV_SMEM ((25344 + 8448 + 128 + 192 + 1088 + 192 + 320 + 4) * 4)

__global__ void __launch_bounds__(512, 1) conv_k(
    int l, int flip, int yrd, int ywr, const float* __restrict__ bond,
    const int* __restrict__ nbrl, const float* __restrict__ cb,
    const float* __restrict__ fb, const float* __restrict__ bag,
    const float* __restrict__ bab, const float* __restrict__ bbg,
    const float* __restrict__ bbb, int do_proj,
    const float* __restrict__ cwn, const float* __restrict__ fwn) {
    extern __shared__ float sm[];
    float* bs = sm;                 // 192 x 132 bond tile (k contiguous)
    float* ws2 = sm + 25344;        // 64 x 132 weights c-major
    float* fs = ws2 + 8448;         // 128 filter weights
    float* ft = fs + 128;           // 192 logits / softmax weights
    float* xb = ft + 192;           // 16 x 68 new-x stash
    int* nb = (int*)(xb + 1088);    // 192 neighbor ids
    float* pb = (float*)(nb + 192); // 5 x 64 params: cb|bag|bab|bbg|bbb
    unsigned mb0 =
        (unsigned)__cvta_generic_to_shared(pb + 320);        // mbarrier 0
    unsigned mb1 = mb0 + 8;                                  // mbarrier 1

    const float* Xc = flip ? g_X1 : g_X0;
    float* Xn = flip ? g_X0 : g_X1;
    const float* Y1r = g_Y1[yrd];
    const float* Y2r = g_Y2[yrd];
    const float* S1r = g_S1[yrd];
    const float* S2r = g_S2[yrd];

    int tid = threadIdx.x;
    int b = blockIdx.x >> 6;
    int n0 = (blockIdx.x & 63) << 4;
    int bn0 = b * 1024 + n0;
    const float* gb = bond + (size_t)bn0 * 12 * 128;

    unsigned bs_s = (unsigned)__cvta_generic_to_shared(bs);
    unsigned ws_s = (unsigned)__cvta_generic_to_shared(ws2);
    unsigned fs_s = (unsigned)__cvta_generic_to_shared(fs);

    if (tid == 0) {
        mbar_init(mb0, 1);
        mbar_init(mb1, 1);
        mbar_expect(mb0, 192 * 256 + 33792 + 512);   // half0 + weights + filt
        mbar_expect(mb1, 192 * 256);                 // half1
    }
    __syncthreads();

    // issue bulk copies (per-row 256B chunks; rows contiguous in gmem)
    if (tid < 192) {
        bulk_cp(bs_s + tid * 528, gb + tid * 128, 256, mb0);
    } else if (tid < 384) {
        int r = tid - 192;
        bulk_cp(bs_s + r * 528 + 256, gb + r * 128 + 64, 256, mb1);
    } else if (tid == 384) {
        bulk_cp(ws_s, &g_WT[l][0], 33792, mb0);
    } else if (tid == 385) {
        bulk_cp(fs_s, &g_FW[l][0], 512, mb0);
    } else if (tid >= 448) {
        int c = tid - 448;
        pb[c] = cb[c];
        pb[64 + c] = bag[c];
        pb[128 + c] = bab[c];
        pb[192 + c] = bbg[c];
        pb[256 + c] = bbb[c];
    }

    int lane = tid & 31, w = tid >> 5;
    int rg = w & 3, cg = w >> 2;
    int rt = lane & 15, ch = lane >> 4;
    int rbase = rg * 48 + rt * 3;
    int cbase = cg * 16 + ch * 8;
    const float* wsb = ws2 + cbase * 132;

    unsigned long long acc[3][8];
#pragma unroll
    for (int i = 0; i < 3; i++)
#pragma unroll
        for (int j = 0; j < 8; j++) acc[i][j] = 0ull;

    for (int half = 0; half < 2; half++) {
        mbar_wait(half ? mb1 : mb0);
#pragma unroll 2
        for (int kk = 0; kk < 64; kk += 4) {
            int k0 = half * 64 + kk;
            ulonglong2 a[3];
#pragma unroll
            for (int i = 0; i < 3; i++)
                a[i] = *(const ulonglong2*)(bs + (rbase + i) * 132 + k0);
#pragma unroll
            for (int j = 0; j < 8; j++) {
                ulonglong2 bv = *(const ulonglong2*)(wsb + j * 132 + k0);
#pragma unroll
                for (int i = 0; i < 3; i++) {
                    fma2(acc[i][j], a[i].x, bv.x);
                    fma2(acc[i][j], a[i].y, bv.y);
                }
            }
        }
    }

    // filter logits (read bond tile before Cs overwrites it)
    if (tid < 192) {
        int row = tid;
        int a_ = row / 12, m = row - a_ * 12;
        int nglob = bn0 + a_;
        int nbr = nbrl[nglob * 12 + m];
        nb[row] = nbr;
        float acc2 = 0.f;
#pragma unroll 8
        for (int k = 0; k < 128; k += 4) {
            float4 bvv = *(const float4*)(bs + row * 132 + k);
            float4 fv = *(const float4*)(fs + k);
            acc2 += bvv.x * fv.x + bvv.y * fv.y + bvv.z * fv.z + bvv.w * fv.w;
        }
        ft[row] = acc2 + S1r[nglob] + S2r[b * 1024 + nbr] + fb[0];
    }
    __syncthreads();

    // softmax over m (folding the 1/12 mean)
    if (tid < 16) {
        int base = tid * 12;
        float mx = -1e30f;
#pragma unroll
        for (int m = 0; m < 12; m++) mx = fmaxf(mx, ft[base + m]);
        float s = 0.f;
#pragma unroll
        for (int m = 0; m < 12; m++) s += expf(ft[base + m] - mx);
        float inv = 1.f / (12.f * s);
#pragma unroll
        for (int m = 0; m < 12; m++)
            ft[base + m] = expf(ft[base + m] - mx) * inv;
    }

    // core epilogue: C + y1 + y2[nbr] + cb -> BN -> relu -> Cs (reuses bs)
    float* Cs = bs;   // 192 x 65
#pragma unroll
    for (int i = 0; i < 3; i++) {
        int row = rbase + i;
        int a_ = row / 12;
        int nglob = bn0 + a_;
        int nbr = nb[row];
        float4 y1a = *(const float4*)(Y1r + nglob * 64 + cbase);
        float4 y1b = *(const float4*)(Y1r + nglob * 64 + cbase + 4);
        float4 y2a = *(const float4*)(Y2r + (b * 1024 + nbr) * 64 + cbase);
        float4 y2b = *(const float4*)(Y2r + (b * 1024 + nbr) * 64 + cbase + 4);
        float y1v[8] = {y1a.x, y1a.y, y1a.z, y1a.w, y1b.x, y1b.y, y1b.z, y1b.w};
        float y2v[8] = {y2a.x, y2a.y, y2a.z, y2a.w, y2b.x, y2b.y, y2b.z, y2b.w};
#pragma unroll
        for (int j = 0; j < 8; j++) {
            int c = cbase + j;
            float2 t = up2(acc[i][j]);
            float v = t.x + t.y + y1v[j] + y2v[j] + pb[c];
            v = fmaxf(pb[64 + c] * (v * BN_ALPHA) + pb[128 + c], 0.f);
            Cs[row * 65 + c] = v;
        }
    }
    __syncthreads();

    // weighted mean over m, BN, residual relu; stash xn for fused proj
#pragma unroll
    for (int q = 0; q < 2; q++) {
        int idx = tid + 512 * q;   // < 1024
        int a_ = idx >> 6, c = idx & 63;
        float s = 0.f;
#pragma unroll
        for (int m = 0; m < 12; m++)
            s += ft[a_ * 12 + m] * Cs[(a_ * 12 + m) * 65 + c];
        s = pb[192 + c] * (s * BN_ALPHA) + pb[256 + c];
        int gi = (bn0 + a_) * 64 + c;
        float xv = fmaxf(Xc[gi] + s, 0.f);
        Xn[gi] = xv;
        xb[a_ * 68 + c] = xv;
    }

    // fused next-layer projection into the WRITE buffer
    if (do_proj) {
        __syncthreads();
        if (tid < 260) {
            int rg2 = (tid >= 130) ? 1 : 0;
            int c2 = tid - rg2 * 130;
            proj8(xb, bn0, rg2 * 8, c2, ywr, cwn, fwn);
        }
    }
}

// ---------------------------------------------------------------------------
// Final: crys = relu(gather(x, target_index)); out = relu(crys@dense_w + db)
// ---------------------------------------------------------------------------
__global__ void __launch_bounds__(256) final_k(const int* __restrict__ tix,
                                               const float* __restrict__ dw,
                                               const float* __restrict__ db,
                                               float* __restrict__ out) {
    __shared__ float cs[64 * 68];
    __shared__ float wd[64 * 65];
    int b = blockIdx.x, tid = threadIdx.x;
    for (int t = tid; t < 4096; t += 256) {
        int k = t >> 6, f = t & 63;
        wd[k * 65 + f] = dw[t];
    }
    for (int t = tid; t < 1024; t += 256) {
        int j = t >> 4, q = t & 15;
        int ti = tix[b * 64 + j];
        float4 v = *(const float4*)(g_X1 + (b * 1024 + ti) * 64 + q * 4);
        v.x = fmaxf(v.x, 0.f);
        v.y = fmaxf(v.y, 0.f);
        v.z = fmaxf(v.z, 0.f);
        v.w = fmaxf(v.w, 0.f);
        *(float4*)(cs + j * 68 + q * 4) = v;
    }
    __syncthreads();
    for (int t = tid; t < 4096; t += 256) {
        int j = t >> 6, f = t & 63;
        float acc = db[f];
#pragma unroll 8
        for (int k = 0; k < 64; k++) acc += cs[j * 68 + k] * wd[k * 65 + f];
        out[b * 4096 + t] = fmaxf(acc, 0.f);
    }
}

// ---------------------------------------------------------------------------
extern "C" void kernel_launch(void* const* d_in, const int* in_sizes, int n_in,
                              void* d_out, int out_size) {
    const int* atom_types = (const int*)d_in[0];
    const float* bond = (const float*)d_in[1];
    const int* nbrl = (const int*)d_in[2];
    const int* tix = (const int*)d_in[3];
    const float* emb = (const float*)d_in[4];
    const float* core_w = (const float*)d_in[5];
    const float* core_b = (const float*)d_in[6];
    const float* filt_w = (const float*)d_in[7];
    const float* filt_b = (const float*)d_in[8];
    const float* bna_g = (const float*)d_in[9];
    const float* bna_b = (const float*)d_in[10];
    const float* bnb_g = (const float*)d_in[11];
    const float* bnb_b = (const float*)d_in[12];
    const float* dw = (const float*)d_in[13];
    const float* db = (const float*)d_in[14];
    float* out = (float*)d_out;

    cudaFuncSetAttribute(conv_k, cudaFuncAttributeMaxDynamicSharedMemorySize,
                         CONV_SMEM);

    prep_k<<<3, 256>>>(core_w, filt_w);
    embed_proj_k<<<1024, 256>>>(atom_types, emb, core_w, filt_w);
    for (int l = 0; l < 3; l++) {
        int flip = l & 1;
        int yrd = l & 1;
        int ywr = (l + 1) & 1;
        int do_proj = (l < 2) ? 1 : 0;
        const float* cwn = core_w + (l + 1 < 3 ? (l + 1) : l) * 256 * 64;
        const float* fwn = filt_w + (l + 1 < 3 ? (l + 1) : l) * 256;
        conv_k<<<1024, 512, CONV_SMEM>>>(
            l, flip, yrd, ywr, bond, nbrl, core_b + l * 64, filt_b + l,
            bna_g + l * 64, bna_b + l * 64, bnb_g + l * 64, bnb_b + l * 64,
            do_proj, cwn, fwn);
    }
    final_k<<<16, 256>>>(tix, dw, db, out);
}

// round 7
// speedup vs baseline: 1.3193x; 1.0015x over previous
#include <cuda_runtime.h>

// ---------------------------------------------------------------------------
// CGCNN: B=16, N=1024, M=12, F=64, BF=128, N_CONV=3, VOCAB=100
// total@W = x@W1 + gather(x@W2) + bond@W3 ; proj fused into conv/embed.
// Y/S double-buffered across layers (no cross-block race).
// Bond + weights loaded via cp.async.bulk (UBLKCP) under mbarriers.
// ---------------------------------------------------------------------------

#define BN_ALPHA 0.99950037f   // 1/sqrt(1+1e-3)

__device__ float g_X0[16 * 1024 * 64];
__device__ float g_X1[16 * 1024 * 64];
__device__ float g_Y1[2][16 * 1024 * 64];
__device__ float g_Y2[2][16 * 1024 * 64];
__device__ float g_S1[2][16 * 1024];
__device__ float g_S2[2][16 * 1024];
__device__ float g_WT[3][64 * 132];   // transposed+padded core W3 (c-major)
__device__ float g_FW[3][128];        // filter W3

// ---- f32x2 packed FMA helpers ---------------------------------------------
__device__ __forceinline__ void fma2(unsigned long long& d,
                                     unsigned long long a,
                                     unsigned long long b) {
    asm("fma.rn.f32x2 %0, %1, %2, %0;" : "+l"(d) : "l"(a), "l"(b));
}
__device__ __forceinline__ float2 up2(unsigned long long v) {
    unsigned lo, hi;
    asm("mov.b64 {%0, %1}, %2;" : "=r"(lo), "=r"(hi) : "l"(v));
    float2 r;
    r.x = __uint_as_float(lo);
    r.y = __uint_as_float(hi);
    return r;
}

// ---- mbarrier + bulk-copy helpers ------------------------------------------
__device__ __forceinline__ void mbar_init(unsigned mbar, unsigned cnt) {
    asm volatile("mbarrier.init.shared.b64 [%0], %1;" ::"r"(mbar), "r"(cnt)
                 : "memory");
}
__device__ __forceinline__ void mbar_expect(unsigned mbar, unsigned bytes) {
    asm volatile("mbarrier.arrive.expect_tx.shared.b64 _, [%0], %1;" ::"r"(mbar),
                 "r"(bytes)
                 : "memory");
}
__device__ __forceinline__ void mbar_wait(unsigned mbar) {
    asm volatile(
        "{\n\t.reg .pred P;\n\t"
        "W%=:\n\t"
        "mbarrier.try_wait.parity.acquire.cta.shared::cta.b64 P, [%0], 0;\n\t"
        "@!P bra W%=;\n\t}"
        ::"r"(mbar)
        : "memory");
}
__device__ __forceinline__ void bulk_cp(unsigned dst, const void* src,
                                        unsigned bytes, unsigned mbar) {
    asm volatile(
        "cp.async.bulk.shared::cta.global.mbarrier::complete_tx::bytes "
        "[%0], [%1], %2, [%3];" ::"r"(dst),
        "l"(src), "r"(bytes), "r"(mbar)
        : "memory");
}

// ---------------------------------------------------------------------------
// Weight prep: transpose core W3 per layer into c-major padded layout.
// grid 3 blocks x 256 threads.
// ---------------------------------------------------------------------------
__global__ void __launch_bounds__(256) prep_k(const float* __restrict__ cw,
                                              const float* __restrict__ fw) {
    int l = blockIdx.x;
    const float* cw3 = cw + l * 256 * 64 + 128 * 64;
    for (int t = threadIdx.x; t < 8192; t += 256) {
        int k = t >> 6, c = t & 63;
        g_WT[l][c * 132 + k] = cw3[t];
    }
    const float* fw3 = fw + l * 256 + 128;
    if (threadIdx.x < 128) g_FW[l][threadIdx.x] = fw3[threadIdx.x];
}

// ---------------------------------------------------------------------------
// Projection helper: 8 rows of x (smem, stride 68) -> Y1/Y2/S1/S2 buffer yb
// ---------------------------------------------------------------------------
__device__ __forceinline__ void proj8(const float* __restrict__ xs, int bn0,
                                      int r0, int c2, int yb,
                                      const float* __restrict__ cwn,
                                      const float* __restrict__ fwn) {
    const float* wp;
    int st;
    if (c2 < 64) {
        wp = cwn + c2;
        st = 64;
    } else if (c2 < 128) {
        wp = cwn + 64 * 64 + (c2 - 64);
        st = 64;
    } else {
        wp = fwn + (c2 - 128) * 64;
        st = 1;
    }
    float acc[8] = {0.f, 0.f, 0.f, 0.f, 0.f, 0.f, 0.f, 0.f};
#pragma unroll 8
    for (int k = 0; k < 64; k++) {
        float wv = __ldg(wp + k * st);
#pragma unroll
        for (int rr = 0; rr < 8; rr++) acc[rr] += xs[(r0 + rr) * 68 + k] * wv;
    }
    if (c2 < 64) {
#pragma unroll
        for (int rr = 0; rr < 8; rr++)
            g_Y1[yb][(bn0 + r0 + rr) * 64 + c2] = acc[rr];
    } else if (c2 < 128) {
#pragma unroll
        for (int rr = 0; rr < 8; rr++)
            g_Y2[yb][(bn0 + r0 + rr) * 64 + (c2 - 64)] = acc[rr];
    } else if (c2 == 128) {
#pragma unroll
        for (int rr = 0; rr < 8; rr++) g_S1[yb][bn0 + r0 + rr] = acc[rr];
    } else {
#pragma unroll
        for (int rr = 0; rr < 8; rr++) g_S2[yb][bn0 + r0 + rr] = acc[rr];
    }
}

// ---------------------------------------------------------------------------
// Embedding gather + layer-0 projection (writes Y/S buffer 0).
// ---------------------------------------------------------------------------
__global__ void __launch_bounds__(256) embed_proj_k(
    const int* __restrict__ types, const float* __restrict__ emb,
    const float* __restrict__ cwn, const float* __restrict__ fwn) {
    __shared__ float xs[16 * 68];
    int tid = threadIdx.x;
    int bn0 = blockIdx.x * 16;
    {
        int r = tid >> 4, q = tid & 15;
        int node = bn0 + r;
        int t = types[node];
        float4 v = *(const float4*)(emb + t * 64 + q * 4);
        *(float4*)(xs + r * 68 + q * 4) = v;
        *(float4*)(g_X0 + node * 64 + q * 4) = v;
    }
    __syncthreads();
    if (tid < 130) {
        proj8(xs, bn0, 0, tid, 0, cwn, fwn);
        proj8(xs, bn0, 8, tid, 0, cwn, fwn);
    }
}

// ---------------------------------------------------------------------------
// Main conv: one block = 16 atoms (192 rows), 512 threads.
//  Loads: bond tile via 384 x 256B cp.async.bulk (2 k-half mbarrier stages,
//         half 1 overlaps half-0 GEMM); weights via 1 bulk copy.
//  GEMM C[192][64] = bond @ W3, k-split f32x2:
//   16 warps = 4 row-groups (48 rows) x 4 col-groups (16 cols)
//   lane: rt = lane&15 -> 3 consecutive rows, ch = lane>>4 -> 8-col half
//  Epilogue: +y1+y2[nbr]+cb, BN, relu, softmax(filt), weighted mean, BN,
//            residual relu -> Xn; fused next-layer proj (buffer ywr).
// ---------------------------------------------------------------------------
// smem floats: bs 25344 | ws2 8448 | fs 128 | ft 192 | xb 1088 | nb 192 |
//              pb 320 | mbar 4
#define CONV_SMEM ((25344 + 8448 + 128 + 192 + 1088 + 192 + 320 + 4) * 4)

__global__ void __launch_bounds__(512, 1) conv_k(
    int l, int flip, int yrd, int ywr, const float* __restrict__ bond,
    const int* __restrict__ nbrl, const float* __restrict__ cb,
    const float* __restrict__ fb, const float* __restrict__ bag,
    const float* __restrict__ bab, const float* __restrict__ bbg,
    const float* __restrict__ bbb, int do_proj,
    const float* __restrict__ cwn, const float* __restrict__ fwn) {
    extern __shared__ float sm[];
    float* bs = sm;                 // 192 x 132 bond tile (k contiguous)
    float* ws2 = sm + 25344;        // 64 x 132 weights c-major
    float* fs = ws2 + 8448;         // 128 filter weights
    float* ft = fs + 128;           // 192 logits / softmax weights
    float* xb = ft + 192;           // 16 x 68 new-x stash
    int* nb = (int*)(xb + 1088);    // 192 neighbor ids
    float* pb = (float*)(nb + 192); // 5 x 64 params: cb|bag|bab|bbg|bbb
    unsigned mb0 =
        (unsigned)__cvta_generic_to_shared(pb + 320);        // mbarrier 0
    unsigned mb1 = mb0 + 8;                                  // mbarrier 1

    const float* Xc = flip ? g_X1 : g_X0;
    float* Xn = flip ? g_X0 : g_X1;
    const float* Y1r = g_Y1[yrd];
    const float* Y2r = g_Y2[yrd];
    const float* S1r = g_S1[yrd];
    const float* S2r = g_S2[yrd];

    int tid = threadIdx.x;
    int b = blockIdx.x >> 6;
    int n0 = (blockIdx.x & 63) << 4;
    int bn0 = b * 1024 + n0;
    const float* gb = bond + (size_t)bn0 * 12 * 128;

    unsigned bs_s = (unsigned)__cvta_generic_to_shared(bs);
    unsigned ws_s = (unsigned)__cvta_generic_to_shared(ws2);
    unsigned fs_s = (unsigned)__cvta_generic_to_shared(fs);

    if (tid == 0) {
        mbar_init(mb0, 1);
        mbar_init(mb1, 1);
        mbar_expect(mb0, 192 * 256 + 33792 + 512);   // half0 + weights + filt
        mbar_expect(mb1, 192 * 256);                 // half1
    }
    __syncthreads();

    // issue bulk copies (per-row 256B chunks; rows contiguous in gmem)
    if (tid < 192) {
        bulk_cp(bs_s + tid * 528, gb + tid * 128, 256, mb0);
    } else if (tid < 384) {
        int r = tid - 192;
        bulk_cp(bs_s + r * 528 + 256, gb + r * 128 + 64, 256, mb1);
    } else if (tid == 384) {
        bulk_cp(ws_s, &g_WT[l][0], 33792, mb0);
    } else if (tid == 385) {
        bulk_cp(fs_s, &g_FW[l][0], 512, mb0);
    } else if (tid >= 448) {
        int c = tid - 448;
        pb[c] = cb[c];
        pb[64 + c] = bag[c];
        pb[128 + c] = bab[c];
        pb[192 + c] = bbg[c];
        pb[256 + c] = bbb[c];
    }

    int lane = tid & 31, w = tid >> 5;
    int rg = w & 3, cg = w >> 2;
    int rt = lane & 15, ch = lane >> 4;
    int rbase = rg * 48 + rt * 3;
    int cbase = cg * 16 + ch * 8;
    const float* wsb = ws2 + cbase * 132;

    unsigned long long acc[3][8];
#pragma unroll
    for (int i = 0; i < 3; i++)
#pragma unroll
        for (int j = 0; j < 8; j++) acc[i][j] = 0ull;

    for (int half = 0; half < 2; half++) {
        mbar_wait(half ? mb1 : mb0);
#pragma unroll 2
        for (int kk = 0; kk < 64; kk += 4) {
            int k0 = half * 64 + kk;
            ulonglong2 a[3];
#pragma unroll
            for (int i = 0; i < 3; i++)
                a[i] = *(const ulonglong2*)(bs + (rbase + i) * 132 + k0);
#pragma unroll
            for (int j = 0; j < 8; j++) {
                ulonglong2 bv = *(const ulonglong2*)(wsb + j * 132 + k0);
#pragma unroll
                for (int i = 0; i < 3; i++) {
                    fma2(acc[i][j], a[i].x, bv.x);
                    fma2(acc[i][j], a[i].y, bv.y);
                }
            }
        }
    }

    // filter logits (read bond tile before Cs overwrites it)
    if (tid < 192) {
        int row = tid;
        int a_ = row / 12, m = row - a_ * 12;
        int nglob = bn0 + a_;
        int nbr = nbrl[nglob * 12 + m];
        nb[row] = nbr;
        float acc2 = 0.f;
#pragma unroll 8
        for (int k = 0; k < 128; k += 4) {
            float4 bvv = *(const float4*)(bs + row * 132 + k);
            float4 fv = *(const float4*)(fs + k);
            acc2 += bvv.x * fv.x + bvv.y * fv.y + bvv.z * fv.z + bvv.w * fv.w;
        }
        ft[row] = acc2 + S1r[nglob] + S2r[b * 1024 + nbr] + fb[0];
    }
    __syncthreads();

    // softmax over m (folding the 1/12 mean)
    if (tid < 16) {
        int base = tid * 12;
        float mx = -1e30f;
#pragma unroll
        for (int m = 0; m < 12; m++) mx = fmaxf(mx, ft[base + m]);
        float s = 0.f;
#pragma unroll
        for (int m = 0; m < 12; m++) s += expf(ft[base + m] - mx);
        float inv = 1.f / (12.f * s);
#pragma unroll
        for (int m = 0; m < 12; m++)
            ft[base + m] = expf(ft[base + m] - mx) * inv;
    }

    // core epilogue: C + y1 + y2[nbr] + cb -> BN -> relu -> Cs (reuses bs)
    float* Cs = bs;   // 192 x 65
#pragma unroll
    for (int i = 0; i < 3; i++) {
        int row = rbase + i;
        int a_ = row / 12;
        int nglob = bn0 + a_;
        int nbr = nb[row];
        float4 y1a = *(const float4*)(Y1r + nglob * 64 + cbase);
        float4 y1b = *(const float4*)(Y1r + nglob * 64 + cbase + 4);
        float4 y2a = *(const float4*)(Y2r + (b * 1024 + nbr) * 64 + cbase);
        float4 y2b = *(const float4*)(Y2r + (b * 1024 + nbr) * 64 + cbase + 4);
        float y1v[8] = {y1a.x, y1a.y, y1a.z, y1a.w, y1b.x, y1b.y, y1b.z, y1b.w};
        float y2v[8] = {y2a.x, y2a.y, y2a.z, y2a.w, y2b.x, y2b.y, y2b.z, y2b.w};
#pragma unroll
        for (int j = 0; j < 8; j++) {
            int c = cbase + j;
            float2 t = up2(acc[i][j]);
            float v = t.x + t.y + y1v[j] + y2v[j] + pb[c];
            v = fmaxf(pb[64 + c] * (v * BN_ALPHA) + pb[128 + c], 0.f);
            Cs[row * 65 + c] = v;
        }
    }
    __syncthreads();

    // weighted mean over m, BN, residual relu; stash xn for fused proj
#pragma unroll
    for (int q = 0; q < 2; q++) {
        int idx = tid + 512 * q;   // < 1024
        int a_ = idx >> 6, c = idx & 63;
        float s = 0.f;
#pragma unroll
        for (int m = 0; m < 12; m++)
            s += ft[a_ * 12 + m] * Cs[(a_ * 12 + m) * 65 + c];
        s = pb[192 + c] * (s * BN_ALPHA) + pb[256 + c];
        int gi = (bn0 + a_) * 64 + c;
        float xv = fmaxf(Xc[gi] + s, 0.f);
        Xn[gi] = xv;
        xb[a_ * 68 + c] = xv;
    }

    // fused next-layer projection into the WRITE buffer
    if (do_proj) {
        __syncthreads();
        if (tid < 260) {
            int rg2 = (tid >= 130) ? 1 : 0;
            int c2 = tid - rg2 * 130;
            proj8(xb, bn0, rg2 * 8, c2, ywr, cwn, fwn);
        }
    }
}

// ---------------------------------------------------------------------------
// Final: crys = relu(gather(x, target_index)); out = relu(crys@dense_w + db)
// ---------------------------------------------------------------------------
__global__ void __launch_bounds__(256) final_k(const int* __restrict__ tix,
                                               const float* __restrict__ dw,
                                               const float* __restrict__ db,
                                               float* __restrict__ out) {
    __shared__ float cs[64 * 68];
    __shared__ float wd[64 * 65];
    int b = blockIdx.x, tid = threadIdx.x;
    for (int t = tid; t < 4096; t += 256) {
        int k = t >> 6, f = t & 63;
        wd[k * 65 + f] = dw[t];
    }
    for (int t = tid; t < 1024; t += 256) {
        int j = t >> 4, q = t & 15;
        int ti = tix[b * 64 + j];
        float4 v = *(const float4*)(g_X1 + (b * 1024 + ti) * 64 + q * 4);
        v.x = fmaxf(v.x, 0.f);
        v.y = fmaxf(v.y, 0.f);
        v.z = fmaxf(v.z, 0.f);
        v.w = fmaxf(v.w, 0.f);
        *(float4*)(cs + j * 68 + q * 4) = v;
    }
    __syncthreads();
    for (int t = tid; t < 4096; t += 256) {
        int j = t >> 6, f = t & 63;
        float acc = db[f];
#pragma unroll 8
        for (int k = 0; k < 64; k++) acc += cs[j * 68 + k] * wd[k * 65 + f];
        out[b * 4096 + t] = fmaxf(acc, 0.f);
    }
}

// ---------------------------------------------------------------------------
extern "C" void kernel_launch(void* const* d_in, const int* in_sizes, int n_in,
                              void* d_out, int out_size) {
    const int* atom_types = (const int*)d_in[0];
    const float* bond = (const float*)d_in[1];
    const int* nbrl = (const int*)d_in[2];
    const int* tix = (const int*)d_in[3];
    const float* emb = (const float*)d_in[4];
    const float* core_w = (const float*)d_in[5];
    const float* core_b = (const float*)d_in[6];
    const float* filt_w = (const float*)d_in[7];
    const float* filt_b = (const float*)d_in[8];
    const float* bna_g = (const float*)d_in[9];
    const float* bna_b = (const float*)d_in[10];
    const float* bnb_g = (const float*)d_in[11];
    const float* bnb_b = (const float*)d_in[12];
    const float* dw = (const float*)d_in[13];
    const float* db = (const float*)d_in[14];
    float* out = (float*)d_out;

    cudaFuncSetAttribute(conv_k, cudaFuncAttributeMaxDynamicSharedMemorySize,
                         CONV_SMEM);

    prep_k<<<3, 256>>>(core_w, filt_w);
    embed_proj_k<<<1024, 256>>>(atom_types, emb, core_w, filt_w);
    for (int l = 0; l < 3; l++) {
        int flip = l & 1;
        int yrd = l & 1;
        int ywr = (l + 1) & 1;
        int do_proj = (l < 2) ? 1 : 0;
        const float* cwn = core_w + (l + 1 < 3 ? (l + 1) : l) * 256 * 64;
        const float* fwn = filt_w + (l + 1 < 3 ? (l + 1) : l) * 256;
        conv_k<<<1024, 512, CONV_SMEM>>>(
            l, flip, yrd, ywr, bond, nbrl, core_b + l * 64, filt_b + l,
            bna_g + l * 64, bna_b + l * 64, bnb_g + l * 64, bnb_b + l * 64,
            do_proj, cwn, fwn);
    }
    final_k<<<16, 256>>>(tix, dw, db, out);
}